// round 10
// baseline (speedup 1.0000x reference)
#include <cuda_runtime.h>
#include <cuda_fp8.h>
#include <cstdint>
#include <cstddef>

// ---------------- problem dims ----------------
#define MDIM 16384
#define KDIM 4096
#define NDIM 4096

// ---------------- GEMM tiling ----------------
#define BM 128
#define BN 256
#define BK 128            // fp8 bytes per k-step
#define STAGES 4
#define KT (KDIM / BK)    // 32 k-iterations
#define STAGE_A_BYTES (BM * BK)                    // 16 KB
#define STAGE_B_BYTES (BN * BK)                    // 32 KB
#define STAGE_BYTES (STAGE_A_BYTES + STAGE_B_BYTES)  // 48 KB
#define GEMM_SMEM (STAGES * STAGE_BYTES)           // 192 KB

// ---------------- scratch (no allocations allowed) ----------------
__device__ __align__(1024) unsigned char g_xq[(size_t)MDIM * KDIM];   // 64 MB fp8 [M,K]
__device__ __align__(1024) unsigned char g_wqt[(size_t)NDIM * KDIM];  // 16 MB fp8 [N,K]
__device__ unsigned g_amax[2];   // zero at module load; atomicMax idempotent across replays

// ---------------- helpers ----------------
__device__ __forceinline__ uint32_t smem_u32(const void* p) {
    uint32_t a;
    asm("{ .reg .u64 t; cvta.to.shared.u64 t, %1; cvt.u32.u64 %0, t; }" : "=r"(a) : "l"(p));
    return a;
}

__device__ __forceinline__ void cp_async16(uint32_t saddr, const void* gptr) {
    asm volatile("cp.async.cg.shared.global [%0], [%1], 16;" :: "r"(saddr), "l"(gptr) : "memory");
}

#define CP_COMMIT() asm volatile("cp.async.commit_group;" ::: "memory")
#define CP_WAIT2()  asm volatile("cp.async.wait_group 2;" ::: "memory")

__device__ __forceinline__ void ldsm_x4(uint32_t& r0, uint32_t& r1, uint32_t& r2, uint32_t& r3, uint32_t addr) {
    asm volatile("ldmatrix.sync.aligned.m8n8.x4.shared.b16 {%0,%1,%2,%3}, [%4];"
                 : "=r"(r0), "=r"(r1), "=r"(r2), "=r"(r3) : "r"(addr));
}

__device__ __forceinline__ void mma_fp8(float& c0, float& c1, float& c2, float& c3,
                                        uint32_t a0, uint32_t a1, uint32_t a2, uint32_t a3,
                                        uint32_t b0, uint32_t b1) {
    asm volatile(
        "mma.sync.aligned.m16n8k32.row.col.f32.e4m3.e4m3.f32 "
        "{%0,%1,%2,%3}, {%4,%5,%6,%7}, {%8,%9}, {%0,%1,%2,%3};"
        : "+f"(c0), "+f"(c1), "+f"(c2), "+f"(c3)
        : "r"(a0), "r"(a1), "r"(a2), "r"(a3), "r"(b0), "r"(b1));
}

// ---------------- fused absmax (x blocks 0..2047, w blocks 2048..2559) ----------------
__global__ void absmax_kernel(const float4* __restrict__ x, const float4* __restrict__ w) {
    __shared__ float red[8];
    const int b = blockIdx.x;
    const float4* v;
    int n4, slot, bid, nb;
    if (b < 2048) { v = x; n4 = (MDIM / 4) * KDIM; slot = 0; bid = b;        nb = 2048; }
    else          { v = w; n4 = (KDIM / 4) * NDIM; slot = 1; bid = b - 2048; nb = 512;  }

    float m = 0.f;
    for (int i = bid * 256 + threadIdx.x; i < n4; i += nb * 256) {
        float4 t = v[i];
        m = fmaxf(m, fmaxf(fmaxf(fabsf(t.x), fabsf(t.y)), fmaxf(fabsf(t.z), fabsf(t.w))));
    }
    #pragma unroll
    for (int o = 16; o; o >>= 1) m = fmaxf(m, __shfl_xor_sync(0xFFFFFFFFu, m, o));
    const int wid = threadIdx.x >> 5, lane = threadIdx.x & 31;
    if (lane == 0) red[wid] = m;
    __syncthreads();
    if (wid == 0) {
        m = (lane < 8) ? red[lane] : 0.f;
        #pragma unroll
        for (int o = 4; o; o >>= 1) m = fmaxf(m, __shfl_xor_sync(0xFFFFFFFFu, m, o));
        if (lane == 0) atomicMax(&g_amax[slot], __float_as_uint(m));
    }
}

// quantize x [M,K] fp32 -> fp8 e4m3 (same layout); 4 float4 per thread
__global__ void quant_x_kernel(const float4* __restrict__ x) {
    const float s = 448.0f / __uint_as_float(g_amax[0]);
    unsigned i0 = blockIdx.x * 1024 + threadIdx.x;
    #pragma unroll
    for (int j = 0; j < 4; j++) {
        unsigned i = i0 + j * 256;
        float4 v = x[i];
        unsigned lo = __nv_cvt_float2_to_fp8x2(make_float2(v.x * s, v.y * s), __NV_SATFINITE, __NV_E4M3);
        unsigned hi = __nv_cvt_float2_to_fp8x2(make_float2(v.z * s, v.w * s), __NV_SATFINITE, __NV_E4M3);
        reinterpret_cast<unsigned*>(g_xq)[i] = (lo & 0xFFFFu) | (hi << 16);
    }
}

// quantize + transpose w [K,N] fp32 -> wq_t [N,K] fp8; 64x64 tile, vectorized I/O
__global__ void quant_wt_kernel(const float* __restrict__ w) {
    __shared__ unsigned tile[64][17];   // packed 4 n-bytes per word, padded
    const float s = 448.0f / __uint_as_float(g_amax[1]);
    const int n0 = blockIdx.x * 64, k0 = blockIdx.y * 64;
    const int t = threadIdx.x;

    {
        const int r = t >> 4;      // 0..15 (k row base)
        const int c = t & 15;      // float4 column (4 n's)
        #pragma unroll
        for (int j = 0; j < 4; j++) {
            int kl = r + j * 16;
            float4 v = *reinterpret_cast<const float4*>(
                w + (size_t)(k0 + kl) * NDIM + n0 + c * 4);
            unsigned lo = __nv_cvt_float2_to_fp8x2(make_float2(v.x * s, v.y * s), __NV_SATFINITE, __NV_E4M3);
            unsigned hi = __nv_cvt_float2_to_fp8x2(make_float2(v.z * s, v.w * s), __NV_SATFINITE, __NV_E4M3);
            tile[kl][c] = (lo & 0xFFFFu) | (hi << 16);
        }
    }
    __syncthreads();

    {
        const int nl = t >> 2;            // 0..63 (n row)
        const int kc = t & 3;             // 16-byte k chunk
        const unsigned sh = (nl & 3) * 8;
        const int col = nl >> 2;
        unsigned o[4];
        #pragma unroll
        for (int q = 0; q < 4; q++) {
            unsigned b0 = (tile[kc * 16 + q * 4 + 0][col] >> sh) & 0xFFu;
            unsigned b1 = (tile[kc * 16 + q * 4 + 1][col] >> sh) & 0xFFu;
            unsigned b2 = (tile[kc * 16 + q * 4 + 2][col] >> sh) & 0xFFu;
            unsigned b3 = (tile[kc * 16 + q * 4 + 3][col] >> sh) & 0xFFu;
            o[q] = b0 | (b1 << 8) | (b2 << 16) | (b3 << 24);
        }
        *reinterpret_cast<uint4*>(g_wqt + (size_t)(n0 + nl) * KDIM + k0 + kc * 16) =
            make_uint4(o[0], o[1], o[2], o[3]);
    }
}

// ---------------- fp8 GEMM via mma.sync m16n8k32 ----------------
// CTA: 128x256, 16 warps (2x8), warp tile 64x32. 4-stage cp.async pipeline.
// LDSM swizzle folded into per-thread bases: addr = base ^ (ks<<5).
__global__ void __launch_bounds__(512, 1) gemm_kernel(float* __restrict__ out) {
    extern __shared__ __align__(1024) unsigned char smem[];
    const uint32_t sb = smem_u32(smem);

    const int tid = threadIdx.x;
    const int w = tid >> 5, lane = tid & 31;
    const int wm = w & 1;            // m offset 0/64
    const int wn = w >> 1;           // 0..7 -> n offset wn*32

    // ---- CTA raster swizzle: groups of 16(m) x 16(n) CTAs ----
    int lin = blockIdx.y * gridDim.x + blockIdx.x;   // grid = (16, 128)
    int grp = lin >> 8;
    int rem = lin & 255;
    const int m0 = (grp * 16 + (rem & 15)) * BM;
    const int n0 = (rem >> 4) * BN;

    // ---- cp.async mapping: 512 threads, 16B chunks ----
    const int ld_row0 = tid >> 3;              // 0..63
    const int ld_c16  = tid & 7;               // 16B column
    const uint32_t ld_soff = (uint32_t)ld_row0 * BK + (uint32_t)((ld_c16 ^ (ld_row0 & 7)) << 4);
    const size_t   ld_goff = (size_t)ld_row0 * KDIM + (size_t)(ld_c16 << 4);
    const unsigned char* pA = g_xq  + (size_t)m0 * KDIM + ld_goff;
    const unsigned char* pB = g_wqt + (size_t)n0 * KDIM + ld_goff;

    // ---- LDSM per-thread base offsets (swizzle folded; addr = base ^ (ks<<5)) ----
    const int a_kh = lane >> 4;
    const int b_kp = (lane >> 3) & 1;
    uint32_t aOff[4], bOff[2];
    #pragma unroll
    for (int mi = 0; mi < 4; mi++) {
        int r = wm * 64 + mi * 16 + (lane & 15);
        aOff[mi] = (uint32_t)r * BK + (uint32_t)(((r & 7) ^ a_kh) << 4);
    }
    #pragma unroll
    for (int g = 0; g < 2; g++) {
        int r = wn * 32 + g * 16 + (lane & 7) + ((lane >> 4) << 3);
        bOff[g] = (uint32_t)r * BK + (uint32_t)(((r & 7) ^ b_kp) << 4) + STAGE_A_BYTES;
    }

    float acc[4][4][4];
    #pragma unroll
    for (int mi = 0; mi < 4; mi++)
        #pragma unroll
        for (int ni = 0; ni < 4; ni++)
            #pragma unroll
            for (int q = 0; q < 4; q++) acc[mi][ni][q] = 0.f;

    // ---- prologue: load stages 0..2 ----
    #pragma unroll
    for (int s = 0; s < STAGES - 1; s++) {
        uint32_t sA = sb + s * STAGE_BYTES;
        uint32_t sB = sA + STAGE_A_BYTES;
        #pragma unroll
        for (int t = 0; t < 2; t++)
            cp_async16(sA + ld_soff + t * 64 * BK, pA + (size_t)(t * 64) * KDIM);
        #pragma unroll
        for (int t = 0; t < 4; t++)
            cp_async16(sB + ld_soff + t * 64 * BK, pB + (size_t)(t * 64) * KDIM);
        CP_COMMIT();
        pA += BK; pB += BK;
    }

    // ---- mainloop: unrolled over the 4-stage ring ----
    for (int ii = 0; ii < KT; ii += STAGES) {
        #pragma unroll
        for (int u = 0; u < STAGES; u++) {
            const int i = ii + u;
            CP_WAIT2();
            __syncthreads();

            if (i + STAGES - 1 < KT) {
                const int sw_ = (u + STAGES - 1) & (STAGES - 1);
                uint32_t sA = sb + sw_ * STAGE_BYTES;
                uint32_t sB = sA + STAGE_A_BYTES;
                #pragma unroll
                for (int t = 0; t < 2; t++)
                    cp_async16(sA + ld_soff + t * 64 * BK, pA + (size_t)(t * 64) * KDIM);
                #pragma unroll
                for (int t = 0; t < 4; t++)
                    cp_async16(sB + ld_soff + t * 64 * BK, pB + (size_t)(t * 64) * KDIM);
                pA += BK; pB += BK;
            }
            CP_COMMIT();

            // compute stage u (compile-time base)
            const uint32_t stBase = sb + u * STAGE_BYTES;
            uint32_t aAd[4], bAd[2];
            #pragma unroll
            for (int mi = 0; mi < 4; mi++) aAd[mi] = stBase + aOff[mi];
            #pragma unroll
            for (int g = 0; g < 2; g++) bAd[g] = stBase + bOff[g];

            #pragma unroll
            for (int ks = 0; ks < 4; ks++) {
                uint32_t aF[4][4];
                #pragma unroll
                for (int mi = 0; mi < 4; mi++)
                    ldsm_x4(aF[mi][0], aF[mi][1], aF[mi][2], aF[mi][3], aAd[mi] ^ (ks << 5));
                uint32_t bF[8];
                #pragma unroll
                for (int g = 0; g < 2; g++)
                    ldsm_x4(bF[g * 4 + 0], bF[g * 4 + 1], bF[g * 4 + 2], bF[g * 4 + 3], bAd[g] ^ (ks << 5));
                #pragma unroll
                for (int mi = 0; mi < 4; mi++)
                    #pragma unroll
                    for (int ni = 0; ni < 4; ni++)
                        mma_fp8(acc[mi][ni][0], acc[mi][ni][1], acc[mi][ni][2], acc[mi][ni][3],
                                aF[mi][0], aF[mi][1], aF[mi][2], aF[mi][3],
                                bF[ni * 2], bF[ni * 2 + 1]);
            }
        }
    }

    // ---- epilogue: dequant + store ----
    const float ax = __uint_as_float(g_amax[0]);
    const float aw = __uint_as_float(g_amax[1]);
    const float inv = ax * aw * (1.0f / (448.0f * 448.0f));
    #pragma unroll
    for (int mi = 0; mi < 4; mi++) {
        int r = m0 + wm * 64 + mi * 16 + (lane >> 2);
        #pragma unroll
        for (int ni = 0; ni < 4; ni++) {
            int c = n0 + wn * 32 + ni * 8 + 2 * (lane & 3);
            float2 v0 = make_float2(acc[mi][ni][0] * inv, acc[mi][ni][1] * inv);
            float2 v1 = make_float2(acc[mi][ni][2] * inv, acc[mi][ni][3] * inv);
            *reinterpret_cast<float2*>(out + (size_t)r * NDIM + c) = v0;
            *reinterpret_cast<float2*>(out + (size_t)(r + 8) * NDIM + c) = v1;
        }
    }
}

// ---------------- host launch ----------------
extern "C" void kernel_launch(void* const* d_in, const int* in_sizes, int n_in,
                              void* d_out, int out_size) {
    const float* x = (const float*)d_in[0];
    const float* w = (const float*)d_in[1];
    if (n_in >= 2 && in_sizes[0] < in_sizes[1]) { const float* t = x; x = w; w = t; }
    float* out = (float*)d_out;

    absmax_kernel<<<2560, 256>>>((const float4*)x, (const float4*)w);
    quant_x_kernel<<<(MDIM / 4) * (KDIM / 1024), 256>>>((const float4*)x);
    {
        dim3 tg(NDIM / 64, KDIM / 64);
        quant_wt_kernel<<<tg, 256>>>(w);
    }

    cudaFuncSetAttribute(gemm_kernel, cudaFuncAttributeMaxDynamicSharedMemorySize, GEMM_SMEM);
    gemm_kernel<<<dim3(NDIM / BN, MDIM / BM), 512, GEMM_SMEM>>>(out);
}

// round 13
// speedup vs baseline: 1.1156x; 1.1156x over previous
#include <cuda_runtime.h>
#include <cuda.h>
#include <cuda_fp8.h>
#include <cstdint>
#include <cstddef>

// ---------------- problem dims ----------------
#define MDIM 16384
#define KDIM 4096
#define NDIM 4096

// ---------------- GEMM tiling ----------------
#define BM 128
#define BN 256
#define BK 128            // fp8 bytes per k-step
#define STAGES 4
#define KT (KDIM / BK)    // 32 k-iterations
#define STAGE_A_BYTES (BM * BK)                    // 16 KB
#define STAGE_B_BYTES (BN * BK)                    // 32 KB
#define STAGE_BYTES (STAGE_A_BYTES + STAGE_B_BYTES)  // 48 KB
#define SMEM_TILES_OFF 1024
#define GEMM_SMEM (SMEM_TILES_OFF + STAGES * STAGE_BYTES)

// ---------------- scratch (no allocations allowed) ----------------
__device__ __align__(1024) unsigned char g_xq[(size_t)MDIM * KDIM];   // 64 MB fp8 [M,K]
__device__ __align__(1024) unsigned char g_wqt[(size_t)NDIM * KDIM];  // 16 MB fp8 [N,K]
__device__ unsigned g_amax[2];   // zero at module load; atomicMax idempotent across replays

// ---------------- helpers ----------------
__device__ __forceinline__ uint32_t smem_u32(const void* p) {
    uint32_t a;
    asm("{ .reg .u64 t; cvta.to.shared.u64 t, %1; cvt.u32.u64 %0, t; }" : "=r"(a) : "l"(p));
    return a;
}

#define MBAR_INIT(addr, cnt) \
    asm volatile("mbarrier.init.shared.b64 [%0], %1;" :: "r"(addr), "r"(cnt) : "memory")

#define MBAR_EXPECT_TX(addr, bytes) \
    asm volatile("mbarrier.arrive.expect_tx.shared.b64 _, [%0], %1;" :: "r"(addr), "r"(bytes) : "memory")

#define MBAR_ARRIVE(addr) \
    asm volatile("mbarrier.arrive.shared.b64 _, [%0];" :: "r"(addr) : "memory")

#define MBAR_WAIT(addr, phase) do { \
    asm volatile( \
        "{\n\t.reg .pred P;\n\t" \
        "W%=:\n\t" \
        "mbarrier.try_wait.parity.acquire.cta.shared::cta.b64 P, [%0], %1, 0x989680;\n\t" \
        "@P bra.uni D%=;\n\t" \
        "bra.uni W%=;\n\t" \
        "D%=:\n\t}" \
        :: "r"(addr), "r"(phase) : "memory"); \
} while (0)

__device__ __forceinline__ void tma2d(uint32_t dst, const void* map, int cx, int cy, uint32_t mbar) {
    asm volatile(
        "cp.async.bulk.tensor.2d.shared::cta.global.tile.mbarrier::complete_tx::bytes "
        "[%0], [%1, {%2, %3}], [%4];"
        :: "r"(dst), "l"(map), "r"(cx), "r"(cy), "r"(mbar) : "memory");
}

__device__ __forceinline__ void ldsm_x4(uint32_t& r0, uint32_t& r1, uint32_t& r2, uint32_t& r3, uint32_t addr) {
    asm volatile("ldmatrix.sync.aligned.m8n8.x4.shared.b16 {%0,%1,%2,%3}, [%4];"
                 : "=r"(r0), "=r"(r1), "=r"(r2), "=r"(r3) : "r"(addr));
}

__device__ __forceinline__ void mma_fp8(float& c0, float& c1, float& c2, float& c3,
                                        uint32_t a0, uint32_t a1, uint32_t a2, uint32_t a3,
                                        uint32_t b0, uint32_t b1) {
    asm volatile(
        "mma.sync.aligned.m16n8k32.row.col.f32.e4m3.e4m3.f32 "
        "{%0,%1,%2,%3}, {%4,%5,%6,%7}, {%8,%9}, {%0,%1,%2,%3};"
        : "+f"(c0), "+f"(c1), "+f"(c2), "+f"(c3)
        : "r"(a0), "r"(a1), "r"(a2), "r"(a3), "r"(b0), "r"(b1));
}

// ---------------- fused absmax (x blocks 0..2047, w blocks 2048..2559) ----------------
__global__ void absmax_kernel(const float4* __restrict__ x, const float4* __restrict__ w) {
    __shared__ float red[8];
    const int b = blockIdx.x;
    const float4* v;
    int n4, slot, bid, nb;
    if (b < 2048) { v = x; n4 = (MDIM / 4) * KDIM; slot = 0; bid = b;        nb = 2048; }
    else          { v = w; n4 = (KDIM / 4) * NDIM; slot = 1; bid = b - 2048; nb = 512;  }

    float m = 0.f;
    for (int i = bid * 256 + threadIdx.x; i < n4; i += nb * 256) {
        float4 t = v[i];
        m = fmaxf(m, fmaxf(fmaxf(fabsf(t.x), fabsf(t.y)), fmaxf(fabsf(t.z), fabsf(t.w))));
    }
    #pragma unroll
    for (int o = 16; o; o >>= 1) m = fmaxf(m, __shfl_xor_sync(0xFFFFFFFFu, m, o));
    const int wid = threadIdx.x >> 5, lane = threadIdx.x & 31;
    if (lane == 0) red[wid] = m;
    __syncthreads();
    if (wid == 0) {
        m = (lane < 8) ? red[lane] : 0.f;
        #pragma unroll
        for (int o = 4; o; o >>= 1) m = fmaxf(m, __shfl_xor_sync(0xFFFFFFFFu, m, o));
        if (lane == 0) atomicMax(&g_amax[slot], __float_as_uint(m));
    }
}

// quantize x [M,K] fp32 -> fp8 e4m3 (same layout); 4 float4 per thread
__global__ void quant_x_kernel(const float4* __restrict__ x) {
    const float s = 448.0f / __uint_as_float(g_amax[0]);
    unsigned i0 = blockIdx.x * 1024 + threadIdx.x;
    #pragma unroll
    for (int j = 0; j < 4; j++) {
        unsigned i = i0 + j * 256;
        float4 v = x[i];
        unsigned lo = __nv_cvt_float2_to_fp8x2(make_float2(v.x * s, v.y * s), __NV_SATFINITE, __NV_E4M3);
        unsigned hi = __nv_cvt_float2_to_fp8x2(make_float2(v.z * s, v.w * s), __NV_SATFINITE, __NV_E4M3);
        reinterpret_cast<unsigned*>(g_xq)[i] = (lo & 0xFFFFu) | (hi << 16);
    }
}

// quantize + transpose w [K,N] fp32 -> wq_t [N,K] fp8; 64x64 tile, vectorized I/O
__global__ void quant_wt_kernel(const float* __restrict__ w) {
    __shared__ unsigned tile[64][17];
    const float s = 448.0f / __uint_as_float(g_amax[1]);
    const int n0 = blockIdx.x * 64, k0 = blockIdx.y * 64;
    const int t = threadIdx.x;

    {
        const int r = t >> 4;
        const int c = t & 15;
        #pragma unroll
        for (int j = 0; j < 4; j++) {
            int kl = r + j * 16;
            float4 v = *reinterpret_cast<const float4*>(
                w + (size_t)(k0 + kl) * NDIM + n0 + c * 4);
            unsigned lo = __nv_cvt_float2_to_fp8x2(make_float2(v.x * s, v.y * s), __NV_SATFINITE, __NV_E4M3);
            unsigned hi = __nv_cvt_float2_to_fp8x2(make_float2(v.z * s, v.w * s), __NV_SATFINITE, __NV_E4M3);
            tile[kl][c] = (lo & 0xFFFFu) | (hi << 16);
        }
    }
    __syncthreads();

    {
        const int nl = t >> 2;
        const int kc = t & 3;
        const unsigned sh = (nl & 3) * 8;
        const int col = nl >> 2;
        unsigned o[4];
        #pragma unroll
        for (int q = 0; q < 4; q++) {
            unsigned b0 = (tile[kc * 16 + q * 4 + 0][col] >> sh) & 0xFFu;
            unsigned b1 = (tile[kc * 16 + q * 4 + 1][col] >> sh) & 0xFFu;
            unsigned b2 = (tile[kc * 16 + q * 4 + 2][col] >> sh) & 0xFFu;
            unsigned b3 = (tile[kc * 16 + q * 4 + 3][col] >> sh) & 0xFFu;
            o[q] = b0 | (b1 << 8) | (b2 << 16) | (b3 << 24);
        }
        *reinterpret_cast<uint4*>(g_wqt + (size_t)(n0 + nl) * KDIM + k0 + kc * 16) =
            make_uint4(o[0], o[1], o[2], o[3]);
    }
}

// ---------------- fp8 GEMM: TMA operand feed + mma.sync m16n8k32 ----------------
// CTA 128x256, 16 warps, warp tile 64x32, 4-stage TMA pipeline with mbarriers.
// smem layout: [0..63] full[4]+empty[4] mbarriers, tiles at 1024.
__global__ void __launch_bounds__(512, 1) gemm_kernel(
    float* __restrict__ out,
    const __grid_constant__ CUtensorMap tma_a,
    const __grid_constant__ CUtensorMap tma_b)
{
    extern __shared__ __align__(1024) unsigned char smem[];
    const uint32_t sb = smem_u32(smem);

    const int tid = threadIdx.x;
    const int w = tid >> 5, lane = tid & 31;
    const int wm = w & 1;
    const int wn = w >> 1;

    // ---- CTA raster swizzle ----
    int lin = blockIdx.y * gridDim.x + blockIdx.x;   // grid = (16, 128)
    int grp = lin >> 8;
    int rem = lin & 255;
    const int m0 = (grp * 16 + (rem & 15)) * BM;
    const int n0 = (rem >> 4) * BN;

    // mbarriers: full[s] at sb + s*16, empty[s] at sb + 64 + s*16
    const uint32_t FULL0 = sb, EMPTY0 = sb + 64;
    if (tid == 0) {
        #pragma unroll
        for (int s = 0; s < STAGES; s++) {
            MBAR_INIT(FULL0 + s * 16, 1);
            MBAR_INIT(EMPTY0 + s * 16, 512);
        }
        asm volatile("fence.proxy.async.shared::cta;" ::: "memory");
    }
    __syncthreads();

    // ---- ldmatrix per-lane addressing (same swizzle as TMA SW128) ----
    int a_row[4];
    #pragma unroll
    for (int mi = 0; mi < 4; mi++) a_row[mi] = wm * 64 + mi * 16 + (lane & 15);
    const int a_kh = lane >> 4;
    int b_row[2];
    #pragma unroll
    for (int g = 0; g < 2; g++) b_row[g] = wn * 32 + g * 16 + (lane & 7) + ((lane >> 4) << 3);
    const int b_kp = (lane >> 3) & 1;

    float acc[4][4][4];
    #pragma unroll
    for (int mi = 0; mi < 4; mi++)
        #pragma unroll
        for (int ni = 0; ni < 4; ni++)
            #pragma unroll
            for (int q = 0; q < 4; q++) acc[mi][ni][q] = 0.f;

    // ---- prologue: TMA stages 0..2 ----
    if (tid == 0) {
        #pragma unroll
        for (int s = 0; s < STAGES - 1; s++) {
            uint32_t sA = sb + SMEM_TILES_OFF + s * STAGE_BYTES;
            uint32_t full = FULL0 + s * 16;
            MBAR_EXPECT_TX(full, STAGE_BYTES);
            tma2d(sA, &tma_a, s * BK, m0, full);
            tma2d(sA + STAGE_A_BYTES, &tma_b, s * BK, n0, full);
        }
    }

    // ---- mainloop ----
    for (int i = 0; i < KT; ++i) {
        const int s = i & (STAGES - 1);

        // producer: issue TMA for stage i+3 (after its slot is drained)
        if (tid == 0) {
            int j = i + STAGES - 1;
            if (j < KT) {
                int js = j & (STAGES - 1);
                if (j >= STAGES) MBAR_WAIT(EMPTY0 + js * 16, ((j - STAGES) >> 2) & 1);
                uint32_t sA = sb + SMEM_TILES_OFF + js * STAGE_BYTES;
                uint32_t full = FULL0 + js * 16;
                MBAR_EXPECT_TX(full, STAGE_BYTES);
                tma2d(sA, &tma_a, j * BK, m0, full);
                tma2d(sA + STAGE_A_BYTES, &tma_b, j * BK, n0, full);
            }
        }

        // consumer: wait stage i full
        MBAR_WAIT(FULL0 + s * 16, (i >> 2) & 1);

        const uint32_t sA = sb + SMEM_TILES_OFF + s * STAGE_BYTES;
        const uint32_t sB = sA + STAGE_A_BYTES;

        #pragma unroll
        for (int ks = 0; ks < 4; ks++) {
            uint32_t aF[4][4];
            #pragma unroll
            for (int mi = 0; mi < 4; mi++) {
                int r = a_row[mi];
                int c16 = (2 * ks + a_kh) ^ (r & 7);
                ldsm_x4(aF[mi][0], aF[mi][1], aF[mi][2], aF[mi][3],
                        sA + (uint32_t)r * BK + (uint32_t)(c16 << 4));
            }
            uint32_t bF[8];
            #pragma unroll
            for (int g = 0; g < 2; g++) {
                int r = b_row[g];
                int c16 = (2 * ks + b_kp) ^ (r & 7);
                ldsm_x4(bF[g * 4 + 0], bF[g * 4 + 1], bF[g * 4 + 2], bF[g * 4 + 3],
                        sB + (uint32_t)r * BK + (uint32_t)(c16 << 4));
            }
            if (ks == 3) MBAR_ARRIVE(EMPTY0 + s * 16);  // all smem reads done (frags in regs)
            #pragma unroll
            for (int mi = 0; mi < 4; mi++)
                #pragma unroll
                for (int ni = 0; ni < 4; ni++)
                    mma_fp8(acc[mi][ni][0], acc[mi][ni][1], acc[mi][ni][2], acc[mi][ni][3],
                            aF[mi][0], aF[mi][1], aF[mi][2], aF[mi][3],
                            bF[ni * 2], bF[ni * 2 + 1]);
        }
    }

    // ---- epilogue: dequant + store ----
    const float ax = __uint_as_float(g_amax[0]);
    const float aw = __uint_as_float(g_amax[1]);
    const float inv = ax * aw * (1.0f / (448.0f * 448.0f));
    #pragma unroll
    for (int mi = 0; mi < 4; mi++) {
        int r = m0 + wm * 64 + mi * 16 + (lane >> 2);
        #pragma unroll
        for (int ni = 0; ni < 4; ni++) {
            int c = n0 + wn * 32 + ni * 8 + 2 * (lane & 3);
            float2 v0 = make_float2(acc[mi][ni][0] * inv, acc[mi][ni][1] * inv);
            float2 v1 = make_float2(acc[mi][ni][2] * inv, acc[mi][ni][3] * inv);
            *reinterpret_cast<float2*>(out + (size_t)r * NDIM + c) = v0;
            *reinterpret_cast<float2*>(out + (size_t)(r + 8) * NDIM + c) = v1;
        }
    }
}

// ---------------- host launch ----------------
typedef CUresult (*tmap_encode_fn)(
    CUtensorMap*, CUtensorMapDataType, cuuint32_t, void*,
    const cuuint64_t*, const cuuint64_t*, const cuuint32_t*, const cuuint32_t*,
    CUtensorMapInterleave, CUtensorMapSwizzle, CUtensorMapL2promotion, CUtensorMapFloatOOBfill);

extern "C" void kernel_launch(void* const* d_in, const int* in_sizes, int n_in,
                              void* d_out, int out_size) {
    const float* x = (const float*)d_in[0];
    const float* w = (const float*)d_in[1];
    if (n_in >= 2 && in_sizes[0] < in_sizes[1]) { const float* t = x; x = w; w = t; }
    float* out = (float*)d_out;

    absmax_kernel<<<2560, 256>>>((const float4*)x, (const float4*)w);
    quant_x_kernel<<<(MDIM / 4) * (KDIM / 1024), 256>>>((const float4*)x);
    {
        dim3 tg(NDIM / 64, KDIM / 64);
        quant_wt_kernel<<<tg, 256>>>(w);
    }

    void* xq_p = nullptr; void* wq_p = nullptr;
    cudaGetSymbolAddress(&xq_p, g_xq);
    cudaGetSymbolAddress(&wq_p, g_wqt);

    tmap_encode_fn enc = nullptr;
    cudaDriverEntryPointQueryResult qr;
    cudaGetDriverEntryPoint("cuTensorMapEncodeTiled", (void**)&enc, cudaEnableDefault, &qr);

    CUtensorMap tmA, tmB;
    {
        cuuint64_t dims[2] = {KDIM, MDIM};
        cuuint64_t str[1]  = {KDIM};
        cuuint32_t box[2]  = {BK, BM};
        cuuint32_t es[2]   = {1, 1};
        enc(&tmA, CU_TENSOR_MAP_DATA_TYPE_UINT8, 2, xq_p, dims, str, box, es,
            CU_TENSOR_MAP_INTERLEAVE_NONE, CU_TENSOR_MAP_SWIZZLE_128B,
            CU_TENSOR_MAP_L2_PROMOTION_L2_128B, CU_TENSOR_MAP_FLOAT_OOB_FILL_NONE);
    }
    {
        cuuint64_t dims[2] = {KDIM, NDIM};
        cuuint64_t str[1]  = {KDIM};
        cuuint32_t box[2]  = {BK, BN};
        cuuint32_t es[2]   = {1, 1};
        enc(&tmB, CU_TENSOR_MAP_DATA_TYPE_UINT8, 2, wq_p, dims, str, box, es,
            CU_TENSOR_MAP_INTERLEAVE_NONE, CU_TENSOR_MAP_SWIZZLE_128B,
            CU_TENSOR_MAP_L2_PROMOTION_L2_128B, CU_TENSOR_MAP_FLOAT_OOB_FILL_NONE);
    }

    cudaFuncSetAttribute(gemm_kernel, cudaFuncAttributeMaxDynamicSharedMemorySize, GEMM_SMEM);
    gemm_kernel<<<dim3(NDIM / BN, MDIM / BM), 512, GEMM_SMEM>>>(out, tmA, tmB);
}

// round 14
// speedup vs baseline: 1.1638x; 1.0432x over previous
#include <cuda_runtime.h>
#include <cuda.h>
#include <cuda_fp8.h>
#include <cstdint>
#include <cstddef>

// ---------------- problem dims ----------------
#define MDIM 16384
#define KDIM 4096
#define NDIM 4096

// ---------------- GEMM tiling ----------------
#define BM 128
#define BN 128
#define BK 128            // fp8 bytes per k-step
#define STAGES 3
#define KT (KDIM / BK)    // 32 k-iterations
#define STAGE_A_BYTES (BM * BK)                    // 16 KB
#define STAGE_B_BYTES (BN * BK)                    // 16 KB
#define STAGE_BYTES (STAGE_A_BYTES + STAGE_B_BYTES)  // 32 KB
#define SMEM_TILES_OFF 1024
#define GEMM_SMEM (SMEM_TILES_OFF + STAGES * STAGE_BYTES)   // 99328 -> 2 CTAs/SM

// ---------------- scratch (no allocations allowed) ----------------
__device__ __align__(1024) unsigned char g_xq[(size_t)MDIM * KDIM];   // 64 MB fp8 [M,K]
__device__ __align__(1024) unsigned char g_wqt[(size_t)NDIM * KDIM];  // 16 MB fp8 [N,K]
__device__ unsigned g_amax[2];   // zero at module load; atomicMax idempotent across replays

// ---------------- helpers ----------------
__device__ __forceinline__ uint32_t smem_u32(const void* p) {
    uint32_t a;
    asm("{ .reg .u64 t; cvta.to.shared.u64 t, %1; cvt.u32.u64 %0, t; }" : "=r"(a) : "l"(p));
    return a;
}

#define MBAR_INIT(addr, cnt) \
    asm volatile("mbarrier.init.shared.b64 [%0], %1;" :: "r"(addr), "r"(cnt) : "memory")

#define MBAR_EXPECT_TX(addr, bytes) \
    asm volatile("mbarrier.arrive.expect_tx.shared.b64 _, [%0], %1;" :: "r"(addr), "r"(bytes) : "memory")

#define MBAR_ARRIVE(addr) \
    asm volatile("mbarrier.arrive.shared.b64 _, [%0];" :: "r"(addr) : "memory")

#define MBAR_WAIT(addr, phase) do { \
    asm volatile( \
        "{\n\t.reg .pred P;\n\t" \
        "W%=:\n\t" \
        "mbarrier.try_wait.parity.acquire.cta.shared::cta.b64 P, [%0], %1, 0x989680;\n\t" \
        "@P bra.uni D%=;\n\t" \
        "bra.uni W%=;\n\t" \
        "D%=:\n\t}" \
        :: "r"(addr), "r"(phase) : "memory"); \
} while (0)

__device__ __forceinline__ void tma2d(uint32_t dst, const void* map, int cx, int cy, uint32_t mbar) {
    asm volatile(
        "cp.async.bulk.tensor.2d.shared::cta.global.tile.mbarrier::complete_tx::bytes "
        "[%0], [%1, {%2, %3}], [%4];"
        :: "r"(dst), "l"(map), "r"(cx), "r"(cy), "r"(mbar) : "memory");
}

__device__ __forceinline__ void ldsm_x4(uint32_t& r0, uint32_t& r1, uint32_t& r2, uint32_t& r3, uint32_t addr) {
    asm volatile("ldmatrix.sync.aligned.m8n8.x4.shared.b16 {%0,%1,%2,%3}, [%4];"
                 : "=r"(r0), "=r"(r1), "=r"(r2), "=r"(r3) : "r"(addr));
}

__device__ __forceinline__ void mma_fp8(float& c0, float& c1, float& c2, float& c3,
                                        uint32_t a0, uint32_t a1, uint32_t a2, uint32_t a3,
                                        uint32_t b0, uint32_t b1) {
    asm volatile(
        "mma.sync.aligned.m16n8k32.row.col.f32.e4m3.e4m3.f32 "
        "{%0,%1,%2,%3}, {%4,%5,%6,%7}, {%8,%9}, {%0,%1,%2,%3};"
        : "+f"(c0), "+f"(c1), "+f"(c2), "+f"(c3)
        : "r"(a0), "r"(a1), "r"(a2), "r"(a3), "r"(b0), "r"(b1));
}

// ---------------- fused absmax (x blocks 0..2047, w blocks 2048..2559) ----------------
__global__ void absmax_kernel(const float4* __restrict__ x, const float4* __restrict__ w) {
    __shared__ float red[8];
    const int b = blockIdx.x;
    const float4* v;
    int n4, slot, bid, nb;
    if (b < 2048) { v = x; n4 = (MDIM / 4) * KDIM; slot = 0; bid = b;        nb = 2048; }
    else          { v = w; n4 = (KDIM / 4) * NDIM; slot = 1; bid = b - 2048; nb = 512;  }

    float m = 0.f;
    for (int i = bid * 256 + threadIdx.x; i < n4; i += nb * 256) {
        float4 t = v[i];
        m = fmaxf(m, fmaxf(fmaxf(fabsf(t.x), fabsf(t.y)), fmaxf(fabsf(t.z), fabsf(t.w))));
    }
    #pragma unroll
    for (int o = 16; o; o >>= 1) m = fmaxf(m, __shfl_xor_sync(0xFFFFFFFFu, m, o));
    const int wid = threadIdx.x >> 5, lane = threadIdx.x & 31;
    if (lane == 0) red[wid] = m;
    __syncthreads();
    if (wid == 0) {
        m = (lane < 8) ? red[lane] : 0.f;
        #pragma unroll
        for (int o = 4; o; o >>= 1) m = fmaxf(m, __shfl_xor_sync(0xFFFFFFFFu, m, o));
        if (lane == 0) atomicMax(&g_amax[slot], __float_as_uint(m));
    }
}

// quantize x [M,K] fp32 -> fp8 e4m3 (same layout); 4 float4 per thread
__global__ void quant_x_kernel(const float4* __restrict__ x) {
    const float s = 448.0f / __uint_as_float(g_amax[0]);
    unsigned i0 = blockIdx.x * 1024 + threadIdx.x;
    #pragma unroll
    for (int j = 0; j < 4; j++) {
        unsigned i = i0 + j * 256;
        float4 v = x[i];
        unsigned lo = __nv_cvt_float2_to_fp8x2(make_float2(v.x * s, v.y * s), __NV_SATFINITE, __NV_E4M3);
        unsigned hi = __nv_cvt_float2_to_fp8x2(make_float2(v.z * s, v.w * s), __NV_SATFINITE, __NV_E4M3);
        reinterpret_cast<unsigned*>(g_xq)[i] = (lo & 0xFFFFu) | (hi << 16);
    }
}

// quantize + transpose w [K,N] fp32 -> wq_t [N,K] fp8; 64x64 tile, vectorized I/O
__global__ void quant_wt_kernel(const float* __restrict__ w) {
    __shared__ unsigned tile[64][17];
    const float s = 448.0f / __uint_as_float(g_amax[1]);
    const int n0 = blockIdx.x * 64, k0 = blockIdx.y * 64;
    const int t = threadIdx.x;

    {
        const int r = t >> 4;
        const int c = t & 15;
        #pragma unroll
        for (int j = 0; j < 4; j++) {
            int kl = r + j * 16;
            float4 v = *reinterpret_cast<const float4*>(
                w + (size_t)(k0 + kl) * NDIM + n0 + c * 4);
            unsigned lo = __nv_cvt_float2_to_fp8x2(make_float2(v.x * s, v.y * s), __NV_SATFINITE, __NV_E4M3);
            unsigned hi = __nv_cvt_float2_to_fp8x2(make_float2(v.z * s, v.w * s), __NV_SATFINITE, __NV_E4M3);
            tile[kl][c] = (lo & 0xFFFFu) | (hi << 16);
        }
    }
    __syncthreads();

    {
        const int nl = t >> 2;
        const int kc = t & 3;
        const unsigned sh = (nl & 3) * 8;
        const int col = nl >> 2;
        unsigned o[4];
        #pragma unroll
        for (int q = 0; q < 4; q++) {
            unsigned b0 = (tile[kc * 16 + q * 4 + 0][col] >> sh) & 0xFFu;
            unsigned b1 = (tile[kc * 16 + q * 4 + 1][col] >> sh) & 0xFFu;
            unsigned b2 = (tile[kc * 16 + q * 4 + 2][col] >> sh) & 0xFFu;
            unsigned b3 = (tile[kc * 16 + q * 4 + 3][col] >> sh) & 0xFFu;
            o[q] = b0 | (b1 << 8) | (b2 << 16) | (b3 << 24);
        }
        *reinterpret_cast<uint4*>(g_wqt + (size_t)(n0 + nl) * KDIM + k0 + kc * 16) =
            make_uint4(o[0], o[1], o[2], o[3]);
    }
}

// ---------------- fp8 GEMM: TMA feed + mma.sync m16n8k32, 2 CTAs/SM ----------------
// CTA 128x128, 8 warps (2x4), warp tile 64x32. 3-stage TMA pipeline, mbarriers.
__global__ void __launch_bounds__(256, 2) gemm_kernel(
    float* __restrict__ out,
    const __grid_constant__ CUtensorMap tma_a,
    const __grid_constant__ CUtensorMap tma_b)
{
    extern __shared__ __align__(1024) unsigned char smem[];
    const uint32_t sb = smem_u32(smem);

    const int tid = threadIdx.x;
    const int w = tid >> 5, lane = tid & 31;
    const int wm = w & 1;            // m offset 0/64
    const int wn = w >> 1;           // 0..3 -> n offset wn*32

    // ---- CTA raster swizzle: 16(m) x 16(n) tile groups ----
    // grid = (32, 128): 4096 CTAs; m-tiles 128, n-tiles 32.
    int lin = blockIdx.y * gridDim.x + blockIdx.x;
    int grp = lin >> 8;              // 0..15
    int rem = lin & 255;
    int grp_m = grp >> 1;            // 0..7
    int grp_n = grp & 1;             // 0..1
    const int m0 = (grp_m * 16 + (rem & 15)) * BM;
    const int n0 = (grp_n * 16 + (rem >> 4)) * BN;

    // mbarriers: full[s] at sb + s*16, empty[s] at sb + 64 + s*16
    const uint32_t FULL0 = sb, EMPTY0 = sb + 64;
    if (tid == 0) {
        #pragma unroll
        for (int s = 0; s < STAGES; s++) {
            MBAR_INIT(FULL0 + s * 16, 1);
            MBAR_INIT(EMPTY0 + s * 16, 256);
        }
        asm volatile("fence.proxy.async.shared::cta;" ::: "memory");
    }
    __syncthreads();

    // ---- ldmatrix per-lane addressing (matches TMA SW128 swizzle) ----
    int a_row[4];
    #pragma unroll
    for (int mi = 0; mi < 4; mi++) a_row[mi] = wm * 64 + mi * 16 + (lane & 15);
    const int a_kh = lane >> 4;
    int b_row[2];
    #pragma unroll
    for (int g = 0; g < 2; g++) b_row[g] = wn * 32 + g * 16 + (lane & 7) + ((lane >> 4) << 3);
    const int b_kp = (lane >> 3) & 1;

    float acc[4][4][4];
    #pragma unroll
    for (int mi = 0; mi < 4; mi++)
        #pragma unroll
        for (int ni = 0; ni < 4; ni++)
            #pragma unroll
            for (int q = 0; q < 4; q++) acc[mi][ni][q] = 0.f;

    // ---- prologue: TMA stages 0..1 ----
    if (tid == 0) {
        #pragma unroll
        for (int s = 0; s < STAGES - 1; s++) {
            uint32_t sA = sb + SMEM_TILES_OFF + s * STAGE_BYTES;
            uint32_t full = FULL0 + s * 16;
            MBAR_EXPECT_TX(full, STAGE_BYTES);
            tma2d(sA, &tma_a, s * BK, m0, full);
            tma2d(sA + STAGE_A_BYTES, &tma_b, s * BK, n0, full);
        }
    }

    // phase/stage counters (STAGES=3, not a power of 2)
    int cs = 0, cph = 0;                 // consumer full-wait
    int ps = STAGES - 1;                 // producer slot for j = i + STAGES-1
    int pe_ph = 0, pe_cnt = 0;           // producer empty-wait phase tracking

    // ---- mainloop ----
    for (int i = 0; i < KT; ++i) {
        // producer: issue TMA for stage j = i + STAGES-1
        if (tid == 0) {
            int j = i + STAGES - 1;
            if (j < KT) {
                if (j >= STAGES) {
                    MBAR_WAIT(EMPTY0 + ps * 16, pe_ph);
                    if (++pe_cnt == STAGES) { pe_cnt = 0; pe_ph ^= 1; }
                }
                uint32_t sA = sb + SMEM_TILES_OFF + ps * STAGE_BYTES;
                uint32_t full = FULL0 + ps * 16;
                MBAR_EXPECT_TX(full, STAGE_BYTES);
                tma2d(sA, &tma_a, j * BK, m0, full);
                tma2d(sA + STAGE_A_BYTES, &tma_b, j * BK, n0, full);
                if (++ps == STAGES) ps = 0;
            }
        }

        // consumer: wait stage full
        MBAR_WAIT(FULL0 + cs * 16, cph);

        const uint32_t sA = sb + SMEM_TILES_OFF + cs * STAGE_BYTES;
        const uint32_t sB = sA + STAGE_A_BYTES;

        #pragma unroll
        for (int ks = 0; ks < 4; ks++) {
            uint32_t aF[4][4];
            #pragma unroll
            for (int mi = 0; mi < 4; mi++) {
                int r = a_row[mi];
                int c16 = (2 * ks + a_kh) ^ (r & 7);
                ldsm_x4(aF[mi][0], aF[mi][1], aF[mi][2], aF[mi][3],
                        sA + (uint32_t)r * BK + (uint32_t)(c16 << 4));
            }
            uint32_t bF[8];
            #pragma unroll
            for (int g = 0; g < 2; g++) {
                int r = b_row[g];
                int c16 = (2 * ks + b_kp) ^ (r & 7);
                ldsm_x4(bF[g * 4 + 0], bF[g * 4 + 1], bF[g * 4 + 2], bF[g * 4 + 3],
                        sB + (uint32_t)r * BK + (uint32_t)(c16 << 4));
            }
            if (ks == 3) MBAR_ARRIVE(EMPTY0 + cs * 16);  // frags in regs; slot reusable
            #pragma unroll
            for (int mi = 0; mi < 4; mi++)
                #pragma unroll
                for (int ni = 0; ni < 4; ni++)
                    mma_fp8(acc[mi][ni][0], acc[mi][ni][1], acc[mi][ni][2], acc[mi][ni][3],
                            aF[mi][0], aF[mi][1], aF[mi][2], aF[mi][3],
                            bF[ni * 2], bF[ni * 2 + 1]);
        }

        if (++cs == STAGES) { cs = 0; cph ^= 1; }
    }

    // ---- epilogue: dequant + store ----
    const float ax = __uint_as_float(g_amax[0]);
    const float aw = __uint_as_float(g_amax[1]);
    const float inv = ax * aw * (1.0f / (448.0f * 448.0f));
    #pragma unroll
    for (int mi = 0; mi < 4; mi++) {
        int r = m0 + wm * 64 + mi * 16 + (lane >> 2);
        #pragma unroll
        for (int ni = 0; ni < 4; ni++) {
            int c = n0 + wn * 32 + ni * 8 + 2 * (lane & 3);
            float2 v0 = make_float2(acc[mi][ni][0] * inv, acc[mi][ni][1] * inv);
            float2 v1 = make_float2(acc[mi][ni][2] * inv, acc[mi][ni][3] * inv);
            *reinterpret_cast<float2*>(out + (size_t)r * NDIM + c) = v0;
            *reinterpret_cast<float2*>(out + (size_t)(r + 8) * NDIM + c) = v1;
        }
    }
}

// ---------------- host launch ----------------
typedef CUresult (*tmap_encode_fn)(
    CUtensorMap*, CUtensorMapDataType, cuuint32_t, void*,
    const cuuint64_t*, const cuuint64_t*, const cuuint32_t*, const cuuint32_t*,
    CUtensorMapInterleave, CUtensorMapSwizzle, CUtensorMapL2promotion, CUtensorMapFloatOOBfill);

extern "C" void kernel_launch(void* const* d_in, const int* in_sizes, int n_in,
                              void* d_out, int out_size) {
    const float* x = (const float*)d_in[0];
    const float* w = (const float*)d_in[1];
    if (n_in >= 2 && in_sizes[0] < in_sizes[1]) { const float* t = x; x = w; w = t; }
    float* out = (float*)d_out;

    absmax_kernel<<<2560, 256>>>((const float4*)x, (const float4*)w);
    quant_x_kernel<<<(MDIM / 4) * (KDIM / 1024), 256>>>((const float4*)x);
    {
        dim3 tg(NDIM / 64, KDIM / 64);
        quant_wt_kernel<<<tg, 256>>>(w);
    }

    void* xq_p = nullptr; void* wq_p = nullptr;
    cudaGetSymbolAddress(&xq_p, g_xq);
    cudaGetSymbolAddress(&wq_p, g_wqt);

    tmap_encode_fn enc = nullptr;
    cudaDriverEntryPointQueryResult qr;
    cudaGetDriverEntryPoint("cuTensorMapEncodeTiled", (void**)&enc, cudaEnableDefault, &qr);

    CUtensorMap tmA, tmB;
    {
        cuuint64_t dims[2] = {KDIM, MDIM};
        cuuint64_t str[1]  = {KDIM};
        cuuint32_t box[2]  = {BK, BM};
        cuuint32_t es[2]   = {1, 1};
        enc(&tmA, CU_TENSOR_MAP_DATA_TYPE_UINT8, 2, xq_p, dims, str, box, es,
            CU_TENSOR_MAP_INTERLEAVE_NONE, CU_TENSOR_MAP_SWIZZLE_128B,
            CU_TENSOR_MAP_L2_PROMOTION_L2_128B, CU_TENSOR_MAP_FLOAT_OOB_FILL_NONE);
    }
    {
        cuuint64_t dims[2] = {KDIM, NDIM};
        cuuint64_t str[1]  = {KDIM};
        cuuint32_t box[2]  = {BK, BN};
        cuuint32_t es[2]   = {1, 1};
        enc(&tmB, CU_TENSOR_MAP_DATA_TYPE_UINT8, 2, wq_p, dims, str, box, es,
            CU_TENSOR_MAP_INTERLEAVE_NONE, CU_TENSOR_MAP_SWIZZLE_128B,
            CU_TENSOR_MAP_L2_PROMOTION_L2_128B, CU_TENSOR_MAP_FLOAT_OOB_FILL_NONE);
    }

    cudaFuncSetAttribute(gemm_kernel, cudaFuncAttributeMaxDynamicSharedMemorySize, GEMM_SMEM);
    gemm_kernel<<<dim3(NDIM / BN, MDIM / BM), 256, GEMM_SMEM>>>(out, tmA, tmB);
}

// round 15
// speedup vs baseline: 1.2335x; 1.0599x over previous
#include <cuda_runtime.h>
#include <cuda.h>
#include <cuda_fp8.h>
#include <cstdint>
#include <cstddef>

// ---------------- problem dims ----------------
#define MDIM 16384
#define KDIM 4096
#define NDIM 4096

// ---------------- GEMM tiling ----------------
#define BM 128
#define BN 128
#define BK 128            // fp8 bytes per k-step
#define STAGES 3
#define KT (KDIM / BK)    // 32 k-iterations
#define STAGE_A_BYTES (BM * BK)                    // 16 KB
#define STAGE_B_BYTES (BN * BK)                    // 16 KB
#define STAGE_BYTES (STAGE_A_BYTES + STAGE_B_BYTES)  // 32 KB
#define SMEM_TILES_OFF 1024
#define GEMM_SMEM (SMEM_TILES_OFF + STAGES * STAGE_BYTES)   // 99328 -> 2 CTAs/SM

// ---------------- scratch (no allocations allowed) ----------------
__device__ __align__(1024) unsigned char g_xq[(size_t)MDIM * KDIM];   // 64 MB fp8 [M,K]
__device__ __align__(1024) unsigned char g_wqt[(size_t)NDIM * KDIM];  // 16 MB fp8 [N,K]
__device__ unsigned g_amax[2];   // zero at module load; atomicMax idempotent across replays

// ---------------- helpers ----------------
__device__ __forceinline__ uint32_t smem_u32(const void* p) {
    uint32_t a;
    asm("{ .reg .u64 t; cvta.to.shared.u64 t, %1; cvt.u32.u64 %0, t; }" : "=r"(a) : "l"(p));
    return a;
}

#define MBAR_INIT(addr, cnt) \
    asm volatile("mbarrier.init.shared.b64 [%0], %1;" :: "r"(addr), "r"(cnt) : "memory")

#define MBAR_EXPECT_TX(addr, bytes) \
    asm volatile("mbarrier.arrive.expect_tx.shared.b64 _, [%0], %1;" :: "r"(addr), "r"(bytes) : "memory")

#define MBAR_ARRIVE(addr) \
    asm volatile("mbarrier.arrive.shared.b64 _, [%0];" :: "r"(addr) : "memory")

#define MBAR_WAIT(addr, phase) do { \
    asm volatile( \
        "{\n\t.reg .pred P;\n\t" \
        "W%=:\n\t" \
        "mbarrier.try_wait.parity.acquire.cta.shared::cta.b64 P, [%0], %1, 0x989680;\n\t" \
        "@P bra.uni D%=;\n\t" \
        "bra.uni W%=;\n\t" \
        "D%=:\n\t}" \
        :: "r"(addr), "r"(phase) : "memory"); \
} while (0)

__device__ __forceinline__ void tma2d(uint32_t dst, const void* map, int cx, int cy, uint32_t mbar) {
    asm volatile(
        "cp.async.bulk.tensor.2d.shared::cta.global.tile.mbarrier::complete_tx::bytes "
        "[%0], [%1, {%2, %3}], [%4];"
        :: "r"(dst), "l"(map), "r"(cx), "r"(cy), "r"(mbar) : "memory");
}

__device__ __forceinline__ void ldsm_x4(uint32_t& r0, uint32_t& r1, uint32_t& r2, uint32_t& r3, uint32_t addr) {
    asm volatile("ldmatrix.sync.aligned.m8n8.x4.shared.b16 {%0,%1,%2,%3}, [%4];"
                 : "=r"(r0), "=r"(r1), "=r"(r2), "=r"(r3) : "r"(addr));
}

__device__ __forceinline__ void mma_fp8(float& c0, float& c1, float& c2, float& c3,
                                        uint32_t a0, uint32_t a1, uint32_t a2, uint32_t a3,
                                        uint32_t b0, uint32_t b1) {
    asm volatile(
        "mma.sync.aligned.m16n8k32.row.col.f32.e4m3.e4m3.f32 "
        "{%0,%1,%2,%3}, {%4,%5,%6,%7}, {%8,%9}, {%0,%1,%2,%3};"
        : "+f"(c0), "+f"(c1), "+f"(c2), "+f"(c3)
        : "r"(a0), "r"(a1), "r"(a2), "r"(a3), "r"(b0), "r"(b1));
}

// ---------------- fused absmax (x blocks 0..2047, w blocks 2048..2559) ----------------
__global__ void absmax_kernel(const float4* __restrict__ x, const float4* __restrict__ w) {
    __shared__ float red[8];
    const int b = blockIdx.x;
    const float4* v;
    int n4, slot, bid, nb;
    if (b < 2048) { v = x; n4 = (MDIM / 4) * KDIM; slot = 0; bid = b;        nb = 2048; }
    else          { v = w; n4 = (KDIM / 4) * NDIM; slot = 1; bid = b - 2048; nb = 512;  }

    float m = 0.f;
    for (int i = bid * 256 + threadIdx.x; i < n4; i += nb * 256) {
        float4 t = v[i];
        m = fmaxf(m, fmaxf(fmaxf(fabsf(t.x), fabsf(t.y)), fmaxf(fabsf(t.z), fabsf(t.w))));
    }
    #pragma unroll
    for (int o = 16; o; o >>= 1) m = fmaxf(m, __shfl_xor_sync(0xFFFFFFFFu, m, o));
    const int wid = threadIdx.x >> 5, lane = threadIdx.x & 31;
    if (lane == 0) red[wid] = m;
    __syncthreads();
    if (wid == 0) {
        m = (lane < 8) ? red[lane] : 0.f;
        #pragma unroll
        for (int o = 4; o; o >>= 1) m = fmaxf(m, __shfl_xor_sync(0xFFFFFFFFu, m, o));
        if (lane == 0) atomicMax(&g_amax[slot], __float_as_uint(m));
    }
}

// fused quantize: blocks [0, 16384) do x; blocks [16384, 16384+4096) do w-transpose
#define QX_BLOCKS ((MDIM / 4) * (KDIM / 1024))          // 16384
__global__ void quant_kernel(const float4* __restrict__ x, const float* __restrict__ w) {
    if (blockIdx.x < QX_BLOCKS) {
        // ---- x path: [M,K] fp32 -> fp8, same layout; 4 float4 per thread ----
        const float s = 448.0f / __uint_as_float(g_amax[0]);
        unsigned i0 = blockIdx.x * 1024 + threadIdx.x;
        #pragma unroll
        for (int j = 0; j < 4; j++) {
            unsigned i = i0 + j * 256;
            float4 v = x[i];
            unsigned lo = __nv_cvt_float2_to_fp8x2(make_float2(v.x * s, v.y * s), __NV_SATFINITE, __NV_E4M3);
            unsigned hi = __nv_cvt_float2_to_fp8x2(make_float2(v.z * s, v.w * s), __NV_SATFINITE, __NV_E4M3);
            reinterpret_cast<unsigned*>(g_xq)[i] = (lo & 0xFFFFu) | (hi << 16);
        }
        return;
    }
    // ---- w path: quantize + transpose [K,N] -> [N,K]; 64x64 tile ----
    __shared__ unsigned tile[64][17];
    const float s = 448.0f / __uint_as_float(g_amax[1]);
    const int wb = blockIdx.x - QX_BLOCKS;               // 0..4095
    const int n0 = (wb & 63) * 64, k0 = (wb >> 6) * 64;
    const int t = threadIdx.x;
    {
        const int r = t >> 4;
        const int c = t & 15;
        #pragma unroll
        for (int j = 0; j < 4; j++) {
            int kl = r + j * 16;
            float4 v = *reinterpret_cast<const float4*>(
                w + (size_t)(k0 + kl) * NDIM + n0 + c * 4);
            unsigned lo = __nv_cvt_float2_to_fp8x2(make_float2(v.x * s, v.y * s), __NV_SATFINITE, __NV_E4M3);
            unsigned hi = __nv_cvt_float2_to_fp8x2(make_float2(v.z * s, v.w * s), __NV_SATFINITE, __NV_E4M3);
            tile[kl][c] = (lo & 0xFFFFu) | (hi << 16);
        }
    }
    __syncthreads();
    {
        const int nl = t >> 2;
        const int kc = t & 3;
        const unsigned sh = (nl & 3) * 8;
        const int col = nl >> 2;
        unsigned o[4];
        #pragma unroll
        for (int q = 0; q < 4; q++) {
            unsigned b0 = (tile[kc * 16 + q * 4 + 0][col] >> sh) & 0xFFu;
            unsigned b1 = (tile[kc * 16 + q * 4 + 1][col] >> sh) & 0xFFu;
            unsigned b2 = (tile[kc * 16 + q * 4 + 2][col] >> sh) & 0xFFu;
            unsigned b3 = (tile[kc * 16 + q * 4 + 3][col] >> sh) & 0xFFu;
            o[q] = b0 | (b1 << 8) | (b2 << 16) | (b3 << 24);
        }
        *reinterpret_cast<uint4*>(g_wqt + (size_t)(n0 + nl) * KDIM + k0 + kc * 16) =
            make_uint4(o[0], o[1], o[2], o[3]);
    }
}

// ---------------- fp8 GEMM: TMA feed + mma.sync m16n8k32, 2 CTAs/SM ----------------
// CTA 128x128, 8 warps (2x4), warp tile 64x32. 3-stage TMA pipeline, mbarriers.
// Rotating producer (warp i&7), elect-one empty arrive, folded LDSM offsets.
__global__ void __launch_bounds__(256, 2) gemm_kernel(
    float* __restrict__ out,
    const __grid_constant__ CUtensorMap tma_a,
    const __grid_constant__ CUtensorMap tma_b)
{
    extern __shared__ __align__(1024) unsigned char smem[];
    const uint32_t sb = smem_u32(smem);

    const int tid = threadIdx.x;
    const int w = tid >> 5, lane = tid & 31;
    const int wm = w & 1;            // m offset 0/64
    const int wn = w >> 1;           // 0..3 -> n offset wn*32

    // ---- CTA raster swizzle: 16(m) x 16(n) tile groups ----
    int lin = blockIdx.y * gridDim.x + blockIdx.x;
    int grp = lin >> 8;              // 0..15
    int rem = lin & 255;
    int grp_m = grp >> 1;
    int grp_n = grp & 1;
    const int m0 = (grp_m * 16 + (rem & 15)) * BM;
    const int n0 = (grp_n * 16 + (rem >> 4)) * BN;

    // mbarriers: full[s] at sb + s*16, empty[s] at sb + 64 + s*16
    const uint32_t FULL0 = sb, EMPTY0 = sb + 64;
    if (tid == 0) {
        #pragma unroll
        for (int s = 0; s < STAGES; s++) {
            MBAR_INIT(FULL0 + s * 16, 1);
            MBAR_INIT(EMPTY0 + s * 16, 8);     // one arrive per warp
        }
        asm volatile("fence.proxy.async.shared::cta;" ::: "memory");
    }
    __syncthreads();

    // ---- folded LDSM offsets (addr = stageBase + off ^ (ks<<5)) ----
    const int a_kh = lane >> 4;
    const int b_kp = (lane >> 3) & 1;
    uint32_t aOff[4], bOff[2];
    #pragma unroll
    for (int mi = 0; mi < 4; mi++) {
        int r = wm * 64 + mi * 16 + (lane & 15);
        aOff[mi] = (uint32_t)r * BK + (uint32_t)(((r & 7) ^ a_kh) << 4);
    }
    #pragma unroll
    for (int g = 0; g < 2; g++) {
        int r = wn * 32 + g * 16 + (lane & 7) + ((lane >> 4) << 3);
        bOff[g] = (uint32_t)r * BK + (uint32_t)(((r & 7) ^ b_kp) << 4) + STAGE_A_BYTES;
    }

    float acc[4][4][4];
    #pragma unroll
    for (int mi = 0; mi < 4; mi++)
        #pragma unroll
        for (int ni = 0; ni < 4; ni++)
            #pragma unroll
            for (int q = 0; q < 4; q++) acc[mi][ni][q] = 0.f;

    // ---- prologue: TMA stages 0..1 ----
    if (tid == 0) {
        #pragma unroll
        for (int s = 0; s < STAGES - 1; s++) {
            uint32_t sA = sb + SMEM_TILES_OFF + s * STAGE_BYTES;
            uint32_t full = FULL0 + s * 16;
            MBAR_EXPECT_TX(full, STAGE_BYTES);
            tma2d(sA, &tma_a, s * BK, m0, full);
            tma2d(sA + STAGE_A_BYTES, &tma_b, s * BK, n0, full);
        }
    }

    // stage/phase counters (warp-uniform, tracked by ALL threads)
    int cs = 0, cph = 0;                 // consumer full-wait
    int ps = STAGES - 1;                 // producer slot for j = i + STAGES-1
    int pe_ph = 0, pe_cnt = 0;           // producer empty-wait phase

    // ---- mainloop ----
    for (int i = 0; i < KT; ++i) {
        // rotating producer: lane 0 of warp (i&7)
        const int j = i + STAGES - 1;
        if (j < KT) {
            if (tid == ((i & 7) << 5)) {
                if (j >= STAGES) MBAR_WAIT(EMPTY0 + ps * 16, pe_ph);
                uint32_t sA = sb + SMEM_TILES_OFF + ps * STAGE_BYTES;
                uint32_t full = FULL0 + ps * 16;
                MBAR_EXPECT_TX(full, STAGE_BYTES);
                tma2d(sA, &tma_a, j * BK, m0, full);
                tma2d(sA + STAGE_A_BYTES, &tma_b, j * BK, n0, full);
            }
            if (j >= STAGES && ++pe_cnt == STAGES) { pe_cnt = 0; pe_ph ^= 1; }
            if (++ps == STAGES) ps = 0;
        }

        // consumer: wait stage full
        MBAR_WAIT(FULL0 + cs * 16, cph);

        const uint32_t stBase = sb + SMEM_TILES_OFF + cs * STAGE_BYTES;
        uint32_t aAd[4], bAd[2];
        #pragma unroll
        for (int mi = 0; mi < 4; mi++) aAd[mi] = stBase + aOff[mi];
        #pragma unroll
        for (int g = 0; g < 2; g++) bAd[g] = stBase + bOff[g];

        #pragma unroll
        for (int ks = 0; ks < 4; ks++) {
            uint32_t aF[4][4];
            #pragma unroll
            for (int mi = 0; mi < 4; mi++)
                ldsm_x4(aF[mi][0], aF[mi][1], aF[mi][2], aF[mi][3], aAd[mi] ^ (ks << 5));
            uint32_t bF[8];
            #pragma unroll
            for (int g = 0; g < 2; g++)
                ldsm_x4(bF[g * 4 + 0], bF[g * 4 + 1], bF[g * 4 + 2], bF[g * 4 + 3], bAd[g] ^ (ks << 5));
            if (ks == 3 && lane == 0) MBAR_ARRIVE(EMPTY0 + cs * 16);  // frags in regs
            #pragma unroll
            for (int mi = 0; mi < 4; mi++)
                #pragma unroll
                for (int ni = 0; ni < 4; ni++)
                    mma_fp8(acc[mi][ni][0], acc[mi][ni][1], acc[mi][ni][2], acc[mi][ni][3],
                            aF[mi][0], aF[mi][1], aF[mi][2], aF[mi][3],
                            bF[ni * 2], bF[ni * 2 + 1]);
        }

        if (++cs == STAGES) { cs = 0; cph ^= 1; }
    }

    // ---- epilogue: dequant + store ----
    const float ax = __uint_as_float(g_amax[0]);
    const float aw = __uint_as_float(g_amax[1]);
    const float inv = ax * aw * (1.0f / (448.0f * 448.0f));
    #pragma unroll
    for (int mi = 0; mi < 4; mi++) {
        int r = m0 + wm * 64 + mi * 16 + (lane >> 2);
        #pragma unroll
        for (int ni = 0; ni < 4; ni++) {
            int c = n0 + wn * 32 + ni * 8 + 2 * (lane & 3);
            float2 v0 = make_float2(acc[mi][ni][0] * inv, acc[mi][ni][1] * inv);
            float2 v1 = make_float2(acc[mi][ni][2] * inv, acc[mi][ni][3] * inv);
            *reinterpret_cast<float2*>(out + (size_t)r * NDIM + c) = v0;
            *reinterpret_cast<float2*>(out + (size_t)(r + 8) * NDIM + c) = v1;
        }
    }
}

// ---------------- host launch ----------------
typedef CUresult (*tmap_encode_fn)(
    CUtensorMap*, CUtensorMapDataType, cuuint32_t, void*,
    const cuuint64_t*, const cuuint64_t*, const cuuint32_t*, const cuuint32_t*,
    CUtensorMapInterleave, CUtensorMapSwizzle, CUtensorMapL2promotion, CUtensorMapFloatOOBfill);

extern "C" void kernel_launch(void* const* d_in, const int* in_sizes, int n_in,
                              void* d_out, int out_size) {
    const float* x = (const float*)d_in[0];
    const float* w = (const float*)d_in[1];
    if (n_in >= 2 && in_sizes[0] < in_sizes[1]) { const float* t = x; x = w; w = t; }
    float* out = (float*)d_out;

    absmax_kernel<<<2560, 256>>>((const float4*)x, (const float4*)w);
    quant_kernel<<<QX_BLOCKS + (KDIM / 64) * (NDIM / 64), 256>>>((const float4*)x, w);

    void* xq_p = nullptr; void* wq_p = nullptr;
    cudaGetSymbolAddress(&xq_p, g_xq);
    cudaGetSymbolAddress(&wq_p, g_wqt);

    tmap_encode_fn enc = nullptr;
    cudaDriverEntryPointQueryResult qr;
    cudaGetDriverEntryPoint("cuTensorMapEncodeTiled", (void**)&enc, cudaEnableDefault, &qr);

    CUtensorMap tmA, tmB;
    {
        cuuint64_t dims[2] = {KDIM, MDIM};
        cuuint64_t str[1]  = {KDIM};
        cuuint32_t box[2]  = {BK, BM};
        cuuint32_t es[2]   = {1, 1};
        enc(&tmA, CU_TENSOR_MAP_DATA_TYPE_UINT8, 2, xq_p, dims, str, box, es,
            CU_TENSOR_MAP_INTERLEAVE_NONE, CU_TENSOR_MAP_SWIZZLE_128B,
            CU_TENSOR_MAP_L2_PROMOTION_L2_128B, CU_TENSOR_MAP_FLOAT_OOB_FILL_NONE);
    }
    {
        cuuint64_t dims[2] = {KDIM, NDIM};
        cuuint64_t str[1]  = {KDIM};
        cuuint32_t box[2]  = {BK, BN};
        cuuint32_t es[2]   = {1, 1};
        enc(&tmB, CU_TENSOR_MAP_DATA_TYPE_UINT8, 2, wq_p, dims, str, box, es,
            CU_TENSOR_MAP_INTERLEAVE_NONE, CU_TENSOR_MAP_SWIZZLE_128B,
            CU_TENSOR_MAP_L2_PROMOTION_L2_128B, CU_TENSOR_MAP_FLOAT_OOB_FILL_NONE);
    }

    cudaFuncSetAttribute(gemm_kernel, cudaFuncAttributeMaxDynamicSharedMemorySize, GEMM_SMEM);
    gemm_kernel<<<dim3(NDIM / BN, MDIM / BM), 256, GEMM_SMEM>>>(out, tmA, tmB);
}